// round 14
// baseline (speedup 1.0000x reference)
#include <cuda_runtime.h>
#include <cuda_bf16.h>
#include <cuda_fp16.h>
typedef unsigned int u32; typedef unsigned long long u64;

__device__ __align__(16) __nv_bfloat16 g_wt[(size_t)7*512*512];
__device__ __align__(16) __nv_bfloat16 g_qdb[(size_t)8192*512];
__device__ __align__(16) __nv_bfloat16 g_qtb[(size_t)8192*512];
__device__ __align__(16) __nv_bfloat16 g_kdb[(size_t)8192*512];
__device__ __align__(16) __nv_bfloat16 g_ktb[(size_t)8192*512];
__device__ __align__(16) __half        g_vb [(size_t)8192*512];
__device__ __align__(16) __nv_bfloat16 g_ctx[(size_t)8192*512];
__device__ __align__(16) float g_y[(size_t)8192*512];

__device__ __forceinline__ u32 smem_u32(const void* p) {
    u32 a; asm("{ .reg .u64 t; cvta.to.shared.u64 t, %1; cvt.u32.u64 %0, t; }" : "=r"(a) : "l"(p)); return a;
}
__device__ __forceinline__ u32 pack_bf16(float lo, float hi) {
    u32 r; asm("cvt.rn.satfinite.bf16x2.f32 %0, %1, %2;" : "=r"(r) : "f"(hi), "f"(lo)); return r;
}
__device__ __forceinline__ u32 f16pack(float lo, float hi) {
    u32 r; asm("cvt.rn.f16x2.f32 %0, %1, %2;" : "=r"(r) : "f"(hi), "f"(lo)); return r;
}
__device__ __forceinline__ u32 ex2h2(u32 a) {
    u32 r; asm("ex2.approx.f16x2 %0, %1;" : "=r"(r) : "r"(a)); return r;
}
__device__ __forceinline__ u32 hadd2(u32 a, u32 b) {
    u32 r; asm("add.f16x2 %0, %1, %2;" : "=r"(r) : "r"(a), "r"(b)); return r;
}
__device__ __forceinline__ void ldsm4(u32* r, u32 a) {
    asm volatile("ldmatrix.sync.aligned.m8n8.x4.shared.b16 {%0,%1,%2,%3}, [%4];"
        : "=r"(r[0]), "=r"(r[1]), "=r"(r[2]), "=r"(r[3]) : "r"(a));
}
__device__ __forceinline__ void ldsm4t(u32* r, u32 a) {
    asm volatile("ldmatrix.sync.aligned.m8n8.x4.trans.shared.b16 {%0,%1,%2,%3}, [%4];"
        : "=r"(r[0]), "=r"(r[1]), "=r"(r[2]), "=r"(r[3]) : "r"(a));
}
__device__ __forceinline__ void mma16(float* c, const u32* a, u32 b0, u32 b1) {
    asm volatile("mma.sync.aligned.m16n8k16.row.col.f32.bf16.bf16.f32 "
        "{%0,%1,%2,%3}, {%4,%5,%6,%7}, {%8,%9}, {%0,%1,%2,%3};"
        : "+f"(c[0]), "+f"(c[1]), "+f"(c[2]), "+f"(c[3])
        : "r"(a[0]), "r"(a[1]), "r"(a[2]), "r"(a[3]), "r"(b0), "r"(b1));
}
__device__ __forceinline__ void mma16h(float* c, const u32* a, u32 b0, u32 b1) {
    asm volatile("mma.sync.aligned.m16n8k16.row.col.f32.f16.f16.f32 "
        "{%0,%1,%2,%3}, {%4,%5,%6,%7}, {%8,%9}, {%0,%1,%2,%3};"
        : "+f"(c[0]), "+f"(c[1]), "+f"(c[2]), "+f"(c[3])
        : "r"(a[0]), "r"(a[1]), "r"(a[2]), "r"(a[3]), "r"(b0), "r"(b1));
}
__device__ __forceinline__ void cpa16(u32 dst, const void* src) {
    asm volatile("cp.async.cg.shared.global [%0], [%1], 16;" :: "r"(dst), "l"(src));
}
#define CP_COMMIT() asm volatile("cp.async.commit_group;" ::: "memory")
#define CP_WAIT(n)  asm volatile("cp.async.wait_group %0;" :: "n"(n) : "memory")

// ---- weight transpose + bf16: Wt[n][k] = W[k][n], 7 matrices ----
__global__ void wtrans(const float* w0, const float* w1, const float* w2, const float* w3,
                       const float* w4, const float* w5, const float* w6, __nv_bfloat16* dst)
{
    __shared__ float t[32][33];
    const float* W;
    switch (blockIdx.z) { case 0: W=w0; break; case 1: W=w1; break; case 2: W=w2; break;
        case 3: W=w3; break; case 4: W=w4; break; case 5: W=w5; break; default: W=w6; }
    int bx = blockIdx.x*32, by = blockIdx.y*32, tx = threadIdx.x, ty = threadIdx.y;
#pragma unroll
    for (int i = 0; i < 4; ++i) t[ty*4+i][tx] = W[(size_t)(by+ty*4+i)*512 + bx+tx];
    __syncthreads();
    __nv_bfloat16* D = dst + (size_t)blockIdx.z*512*512;
#pragma unroll
    for (int i = 0; i < 4; ++i) D[(size_t)(bx+ty*4+i)*512 + by+tx] = __float2bfloat16(t[tx][ty*4+i]);
}

struct GArgs {
    const void* X0[5]; const __nv_bfloat16* W0[5];
    const float* b0[5]; void* Y[5]; float scale[5];
    const void* X1; const __nv_bfloat16* W1; const float* b1;
    const float* res;
};

// ---- HMMA GEMM: 64x128 CTA tile, 4 warps (1x4, warp tile 64x32), 4 CTAs/SM ----
// stage stride 27648 B: A [64][72] bf16 @0, B [128][72] bf16 @9216
#define GEMM_SMEM 55296
template<bool AFP32, bool OUTF32>
__global__ __launch_bounds__(128, 4)
void mma_gemm(GArgs a)
{
    extern __shared__ __align__(16) char gsm[];
    const u32 smb = smem_u32(gsm);
    const int tid = threadIdx.x, l = tid & 31, w = tid >> 5;
    const int m0 = blockIdx.y*64, n0 = blockIdx.x*128, z = blockIdx.z;
    const void* X0 = a.X0[z]; const __nv_bfloat16* W0 = a.W0[z];
    const float* b0p = a.b0[z]; void* Yout = a.Y[z];
    const float scl = a.scale[z];
    const bool dual = (z == 4);
    const int NCH = dual ? 16 : 8;

    float acc[4][4][4];
#pragma unroll
    for (int i = 0; i < 4; ++i)
#pragma unroll
        for (int j = 0; j < 4; ++j)
#pragma unroll
            for (int q = 0; q < 4; ++q) acc[i][j][q] = 0.0f;

    uint2 aR[8];
    auto ldA = [&](int c) {   // fp32 A chunk 64x64 -> regs (bf16x2)
        const float* Xf = (const float*)((dual && c >= 8) ? a.X1 : X0);
        const int k0 = (c & 7) * 64;
#pragma unroll
        for (int i = 0; i < 8; ++i) {
            int v = i*128 + tid, row = v >> 4, c4 = v & 15;
            float4 x = *(const float4*)(Xf + (size_t)(m0+row)*512 + k0 + c4*4);
            aR[i] = make_uint2(pack_bf16(x.x,x.y), pack_bf16(x.z,x.w));
        }
    };
    auto stsA = [&](int b) {
        __nv_bfloat16* As = (__nv_bfloat16*)(gsm + b*27648);
#pragma unroll
        for (int i = 0; i < 8; ++i) {
            int v = i*128 + tid, row = v >> 4, c4 = v & 15;
            *(uint2*)(As + row*72 + c4*4) = aR[i];
        }
    };
    auto cpA = [&](int c, int b) {   // bf16 A chunk 64x64 via cp.async
        const __nv_bfloat16* Xb = (const __nv_bfloat16*)X0;
        const u32 dA = smb + b*27648;
        const int k0 = (c & 7) * 64;
#pragma unroll
        for (int i = 0; i < 4; ++i) {
            int v = i*128 + tid, row = v >> 3, c8 = v & 7;
            cpa16(dA + (row*72 + c8*8)*2, Xb + (size_t)(m0+row)*512 + k0 + c8*8);
        }
    };
    auto cpB = [&](int c, int b) {   // B chunk 128x64
        const __nv_bfloat16* W = (dual && c >= 8) ? a.W1 : W0;
        const u32 dB = smb + b*27648 + 9216;
        const int k0 = (c & 7) * 64;
#pragma unroll
        for (int i = 0; i < 8; ++i) {
            int v = i*128 + tid, row = v >> 3, c8 = v & 7;
            cpa16(dB + (row*72 + c8*8)*2, W + (size_t)(n0+row)*512 + k0 + c8*8);
        }
    };

    if (AFP32) { ldA(0); stsA(0); } else cpA(0, 0);
    cpB(0, 0); CP_COMMIT();

#pragma unroll 1
    for (int c = 0; c < NCH; ++c) {
        const int buf = c & 1;
        if (c + 1 < NCH) {
            if (AFP32) ldA(c + 1);
            else cpA(c + 1, buf ^ 1);
            cpB(c + 1, buf ^ 1);
            CP_COMMIT(); CP_WAIT(1);
        } else CP_WAIT(0);
        __syncthreads();

        const u32 sA = smb + buf*27648, sB = sA + 9216;
#pragma unroll
        for (int ks = 0; ks < 4; ++ks) {
            u32 af[4][4];
#pragma unroll
            for (int mi = 0; mi < 4; ++mi)
                ldsm4(af[mi], sA + ((mi*16 + (l & 15))*72 + ks*16 + (l >> 4)*8)*2);
#pragma unroll
            for (int ni = 0; ni < 2; ++ni) {
                u32 bf[4];
                ldsm4(bf, sB + ((w*32 + ni*16 + (l & 15))*72 + ks*16 + (l >> 4)*8)*2);
#pragma unroll
                for (int mi = 0; mi < 4; ++mi) {
                    mma16(acc[mi][ni*2],   af[mi], bf[0], bf[2]);
                    mma16(acc[mi][ni*2+1], af[mi], bf[1], bf[3]);
                }
            }
        }
        if (AFP32 && c + 1 < NCH) stsA(buf ^ 1);
        __syncthreads();
    }
#pragma unroll
    for (int mi = 0; mi < 4; ++mi)
#pragma unroll
        for (int nj = 0; nj < 4; ++nj) {
            int gr = m0 + mi*16 + (l >> 2);
            int gc = n0 + w*32 + nj*8 + (l & 3)*2;
            float2 bv = *(const float2*)(b0p + gc);
            if (dual) { float2 b2 = *(const float2*)(a.b1 + gc); bv.x += b2.x; bv.y += b2.y; }
            float* cc = acc[mi][nj];
            if (OUTF32) {
                float* Y = (float*)Yout;
                float2 r0 = *(const float2*)(a.res + (size_t)gr*512 + gc);
                float2 r1 = *(const float2*)(a.res + (size_t)(gr+8)*512 + gc);
                *(float2*)(Y + (size_t)gr*512 + gc)     = make_float2(cc[0]+bv.x+r0.x, cc[1]+bv.y+r0.y);
                *(float2*)(Y + (size_t)(gr+8)*512 + gc) = make_float2(cc[2]+bv.x+r1.x, cc[3]+bv.y+r1.y);
            } else if (dual) {      // V output: fp16
                __half* Y = (__half*)Yout;
                *(u32*)(Y + (size_t)gr*512 + gc)     = f16pack(cc[0]+bv.x, cc[1]+bv.y);
                *(u32*)(Y + (size_t)(gr+8)*512 + gc) = f16pack(cc[2]+bv.x, cc[3]+bv.y);
            } else {
                __nv_bfloat16* Y = (__nv_bfloat16*)Yout;
                *(u32*)(Y + (size_t)gr*512 + gc)     = pack_bf16((cc[0]+bv.x)*scl, (cc[1]+bv.y)*scl);
                *(u32*)(Y + (size_t)(gr+8)*512 + gc) = pack_bf16((cc[2]+bv.x)*scl, (cc[3]+bv.y)*scl);
            }
        }
}

// ---- HMMA flash attention: 4 warps x 32 q-rows; fp16 softmax/PV path ----
// smem: K0 @0 [128][136], K1 @34816, V0 @69632 [128][72], V1 @88064 ; total 106496
#define ATT_SMEM 106496
__global__ __launch_bounds__(128, 2)
void mma_attn(const __nv_bfloat16* __restrict__ qd, const __nv_bfloat16* __restrict__ qt,
              const __nv_bfloat16* __restrict__ kd, const __nv_bfloat16* __restrict__ kt,
              const __half* __restrict__ vb, __nv_bfloat16* __restrict__ ctx)
{
    extern __shared__ __align__(16) char sm[];
    const u32 smb = smem_u32(sm);
    const int tid = threadIdx.x, l = tid & 31, w = tid >> 5;
    const int q0 = blockIdx.x*128, bh = blockIdx.y, b = bh >> 3, h = bh & 7;
    const size_t rbase = (size_t)b*2048*512 + h*64;

#pragma unroll
    for (int i = 0; i < 16; ++i) {
        int v = i*128 + tid, row = v >> 4, c16 = v & 15;
        const __nv_bfloat16* src = (c16 < 8) ? qd : qt;
        uint4 x = *(const uint4*)(src + rbase + (size_t)(q0+row)*512 + (c16 & 7)*8);
        *(uint4*)(sm + (row*136 + c16*8)*2) = x;
    }
    __syncthreads();
    u32 qf[8][2][4];
#pragma unroll
    for (int ks = 0; ks < 8; ++ks)
#pragma unroll
        for (int mb = 0; mb < 2; ++mb)
            ldsm4(qf[ks][mb], smb + ((w*32 + mb*16 + (l & 15))*136 + ks*16 + (l >> 4)*8)*2);
    __syncthreads();

    auto issue = [&](int kti, int buf) {
        const int k0 = kti*128;
        const u32 dK = smb + buf*34816, dV = smb + 69632 + buf*18432;
#pragma unroll
        for (int i = 0; i < 16; ++i) {
            int v = i*128 + tid, row = v >> 4, c16 = v & 15;
            const __nv_bfloat16* src = (c16 < 8) ? kd : kt;
            cpa16(dK + (row*136 + c16*8)*2, src + rbase + (size_t)(k0+row)*512 + (c16 & 7)*8);
        }
#pragma unroll
        for (int i = 0; i < 8; ++i) {
            int v = i*128 + tid, row = v >> 3, c8 = v & 7;
            cpa16(dV + (row*72 + c8*8)*2, vb + rbase + (size_t)(k0+row)*512 + c8*8);
        }
    };

    float octx[2][8][4];
#pragma unroll
    for (int mb = 0; mb < 2; ++mb)
#pragma unroll
        for (int i = 0; i < 8; ++i)
#pragma unroll
            for (int q = 0; q < 4; ++q) octx[mb][i][q] = 0.0f;
    float ls[2][2] = {{0.f,0.f},{0.f,0.f}};

    issue(0, 0); CP_COMMIT();
#pragma unroll 1
    for (int kti = 0; kti < 16; ++kti) {
        if (kti < 15) { issue(kti+1, (kti+1)&1); CP_COMMIT(); CP_WAIT(1); }
        else CP_WAIT(0);
        __syncthreads();
        const u32 sK = smb + (kti&1)*34816, sV = smb + 69632 + (kti&1)*18432;
        u32 lh[2][2] = {{0u,0u},{0u,0u}};

#pragma unroll
        for (int qtr = 0; qtr < 4; ++qtr) {
            float c[2][4][4];
#pragma unroll
            for (int mb = 0; mb < 2; ++mb)
#pragma unroll
                for (int i = 0; i < 4; ++i)
#pragma unroll
                    for (int q = 0; q < 4; ++q) c[mb][i][q] = 0.0f;
#pragma unroll
            for (int ks = 0; ks < 8; ++ks)
#pragma unroll
                for (int kb = 0; kb < 2; ++kb) {
                    u32 bf[4];
                    ldsm4(bf, sK + ((qtr*32 + kb*16 + (l & 15))*136 + ks*16 + (l >> 4)*8)*2);
#pragma unroll
                    for (int mb = 0; mb < 2; ++mb) {
                        mma16(c[mb][kb*2],   qf[ks][mb], bf[0], bf[2]);
                        mma16(c[mb][kb*2+1], qf[ks][mb], bf[1], bf[3]);
                    }
                }
            u32 pa[2][2][4];
#pragma unroll
            for (int mb = 0; mb < 2; ++mb)
#pragma unroll
                for (int kb = 0; kb < 2; ++kb) {
                    u32 a0 = ex2h2(f16pack(c[mb][kb*2][0],   c[mb][kb*2][1]));
                    u32 a1 = ex2h2(f16pack(c[mb][kb*2][2],   c[mb][kb*2][3]));
                    u32 a2 = ex2h2(f16pack(c[mb][kb*2+1][0], c[mb][kb*2+1][1]));
                    u32 a3 = ex2h2(f16pack(c[mb][kb*2+1][2], c[mb][kb*2+1][3]));
                    lh[mb][0] = hadd2(hadd2(lh[mb][0], a0), a2);
                    lh[mb][1] = hadd2(hadd2(lh[mb][1], a1), a3);
                    pa[mb][kb][0] = a0; pa[mb][kb][1] = a1;
                    pa[mb][kb][2] = a2; pa[mb][kb][3] = a3;
                }
#pragma unroll
            for (int kb = 0; kb < 2; ++kb)
#pragma unroll
                for (int nj4 = 0; nj4 < 4; ++nj4) {
                    u32 bf[4];
                    ldsm4t(bf, sV + ((qtr*32 + kb*16 + (l & 15))*72 + nj4*16 + (l >> 4)*8)*2);
#pragma unroll
                    for (int mb = 0; mb < 2; ++mb) {
                        mma16h(octx[mb][2*nj4],   pa[mb][kb], bf[0], bf[1]);
                        mma16h(octx[mb][2*nj4+1], pa[mb][kb], bf[2], bf[3]);
                    }
                }
        }
#pragma unroll
        for (int mb = 0; mb < 2; ++mb)
#pragma unroll
            for (int j = 0; j < 2; ++j) {
                __half2 hv = *reinterpret_cast<__half2*>(&lh[mb][j]);
                float2 fv = __half22float2(hv);
                ls[mb][j] += fv.x + fv.y;
            }
        __syncthreads();
    }
#pragma unroll
    for (int mb = 0; mb < 2; ++mb) {
        ls[mb][0] += __shfl_xor_sync(0xffffffffu, ls[mb][0], 1);
        ls[mb][0] += __shfl_xor_sync(0xffffffffu, ls[mb][0], 2);
        ls[mb][1] += __shfl_xor_sync(0xffffffffu, ls[mb][1], 1);
        ls[mb][1] += __shfl_xor_sync(0xffffffffu, ls[mb][1], 2);
        float inv0 = 1.0f / ls[mb][0], inv1 = 1.0f / ls[mb][1];
        size_t gr = (size_t)(b*2048 + q0 + w*32 + mb*16 + (l >> 2));
#pragma unroll
        for (int nj = 0; nj < 8; ++nj) {
            int gc = h*64 + nj*8 + (l & 3)*2;
            *(u32*)(ctx + gr*512 + gc)     = pack_bf16(octx[mb][nj][0]*inv0, octx[mb][nj][1]*inv0);
            *(u32*)(ctx + (gr+8)*512 + gc) = pack_bf16(octx[mb][nj][2]*inv1, octx[mb][nj][3]*inv1);
        }
    }
}

// ---- LayerNorm rows of 512 ----
__global__ __launch_bounds__(128)
void layernorm(const float* __restrict__ Y, const float* __restrict__ gamma,
               const float* __restrict__ beta, float* __restrict__ out)
{
    __shared__ float rs[4], rss[4];
    const int row = blockIdx.x, tid = threadIdx.x;
    const size_t off = (size_t)row*512 + tid*4;
    float4 val = *(const float4*)(Y + off);
    float s = val.x + val.y + val.z + val.w;
    float ss = val.x*val.x + val.y*val.y + val.z*val.z + val.w*val.w;
#pragma unroll
    for (int o = 16; o > 0; o >>= 1) { s += __shfl_xor_sync(0xffffffffu, s, o); ss += __shfl_xor_sync(0xffffffffu, ss, o); }
    int wid = tid >> 5;
    if ((tid & 31) == 0) { rs[wid] = s; rss[wid] = ss; }
    __syncthreads();
    s = rs[0]+rs[1]+rs[2]+rs[3]; ss = rss[0]+rss[1]+rss[2]+rss[3];
    float mean = s*(1.0f/512), var = ss*(1.0f/512) - mean*mean, rstd = rsqrtf(var + 1e-5f);
    float4 g = *(const float4*)(gamma + tid*4), be = *(const float4*)(beta + tid*4), o;
    o.x = (val.x-mean)*rstd*g.x + be.x; o.y = (val.y-mean)*rstd*g.y + be.y;
    o.z = (val.z-mean)*rstd*g.z + be.z; o.w = (val.w-mean)*rstd*g.w + be.w;
    *(float4*)(out + off) = o;
}

extern "C" void kernel_launch(void* const* d_in, const int* in_sizes, int n_in,
                              void* d_out, int out_size)
{
    const float* Qd = (const float*)d_in[0];  const float* Qt = (const float*)d_in[1];
    const float* Kd = (const float*)d_in[2];  const float* Kt = (const float*)d_in[3];
    const float* Vd = (const float*)d_in[4];  const float* Vt = (const float*)d_in[5];
    const float* bqd = (const float*)d_in[7];
    const float* bqt = (const float*)d_in[9];
    const float* bkd = (const float*)d_in[11];
    const float* bkt = (const float*)d_in[13];
    const float* bvd = (const float*)d_in[15];
    const float* bvt = (const float*)d_in[17];
    const float* bo  = (const float*)d_in[19];
    const float* gamma = (const float*)d_in[20]; const float* beta = (const float*)d_in[21];
    float* out = (float*)d_out;

    __nv_bfloat16 *wt, *qdb, *qtb, *kdb, *ktb, *ctxb; __half* vbp; float* y;
    cudaGetSymbolAddress((void**)&wt,  g_wt);
    cudaGetSymbolAddress((void**)&qdb, g_qdb);
    cudaGetSymbolAddress((void**)&qtb, g_qtb);
    cudaGetSymbolAddress((void**)&kdb, g_kdb);
    cudaGetSymbolAddress((void**)&ktb, g_ktb);
    cudaGetSymbolAddress((void**)&vbp, g_vb);
    cudaGetSymbolAddress((void**)&ctxb, g_ctx);
    cudaGetSymbolAddress((void**)&y,   g_y);

    cudaFuncSetAttribute(mma_attn, cudaFuncAttributeMaxDynamicSharedMemorySize, ATT_SMEM);
    cudaFuncSetAttribute(mma_gemm<true,false>,  cudaFuncAttributeMaxDynamicSharedMemorySize, GEMM_SMEM);
    cudaFuncSetAttribute(mma_gemm<false,true>,  cudaFuncAttributeMaxDynamicSharedMemorySize, GEMM_SMEM);

    wtrans<<<dim3(16,16,7), dim3(32,8)>>>((const float*)d_in[6], (const float*)d_in[8],
        (const float*)d_in[10], (const float*)d_in[12], (const float*)d_in[14],
        (const float*)d_in[16], (const float*)d_in[18], wt);

    size_t W = (size_t)512*512;
    const float QS = 0.18033688011112042f;   // 0.125 * log2(e)

    GArgs p{};
    p.X0[0]=Qd; p.X0[1]=Qt; p.X0[2]=Kd; p.X0[3]=Kt; p.X0[4]=Vd;
    p.W0[0]=wt; p.W0[1]=wt+W; p.W0[2]=wt+2*W; p.W0[3]=wt+3*W; p.W0[4]=wt+4*W;
    p.b0[0]=bqd; p.b0[1]=bqt; p.b0[2]=bkd; p.b0[3]=bkt; p.b0[4]=bvd;
    p.Y[0]=qdb; p.Y[1]=qtb; p.Y[2]=kdb; p.Y[3]=ktb; p.Y[4]=vbp;
    p.scale[0]=QS; p.scale[1]=QS; p.scale[2]=1.f; p.scale[3]=1.f; p.scale[4]=1.f;
    p.X1=Vt; p.W1=wt+5*W; p.b1=bvt;
    mma_gemm<true,false><<<dim3(4,128,5),128,GEMM_SMEM>>>(p);

    mma_attn<<<dim3(16,32),128,ATT_SMEM>>>(qdb, qtb, kdb, ktb, vbp, ctxb);

    GArgs o{};
    o.X0[0]=ctxb; o.W0[0]=wt+6*W; o.b0[0]=bo; o.Y[0]=y; o.scale[0]=1.f; o.res=Qd;
    mma_gemm<false,true><<<dim3(4,128,1),128,GEMM_SMEM>>>(o);

    layernorm<<<8192,128>>>(y, gamma, beta, out);
}

// round 15
// speedup vs baseline: 1.0059x; 1.0059x over previous
#include <cuda_runtime.h>
#include <cuda_bf16.h>
#include <cuda_fp16.h>
typedef unsigned int u32; typedef unsigned long long u64;

__device__ __align__(16) __nv_bfloat16 g_wt[(size_t)7*512*512];
__device__ __align__(16) __nv_bfloat16 g_qdb[(size_t)8192*512];
__device__ __align__(16) __nv_bfloat16 g_qtb[(size_t)8192*512];
__device__ __align__(16) __nv_bfloat16 g_kdb[(size_t)8192*512];
__device__ __align__(16) __nv_bfloat16 g_ktb[(size_t)8192*512];
__device__ __align__(16) __half        g_vb [(size_t)8192*512];
__device__ __align__(16) __nv_bfloat16 g_ctx[(size_t)8192*512];
__device__ __align__(16) float g_y[(size_t)8192*512];

__device__ __forceinline__ u32 smem_u32(const void* p) {
    u32 a; asm("{ .reg .u64 t; cvta.to.shared.u64 t, %1; cvt.u32.u64 %0, t; }" : "=r"(a) : "l"(p)); return a;
}
__device__ __forceinline__ u32 pack_bf16(float lo, float hi) {
    u32 r; asm("cvt.rn.satfinite.bf16x2.f32 %0, %1, %2;" : "=r"(r) : "f"(hi), "f"(lo)); return r;
}
__device__ __forceinline__ u32 f16pack(float lo, float hi) {
    u32 r; asm("cvt.rn.f16x2.f32 %0, %1, %2;" : "=r"(r) : "f"(hi), "f"(lo)); return r;
}
__device__ __forceinline__ u32 ex2h2(u32 a) {
    u32 r; asm("ex2.approx.f16x2 %0, %1;" : "=r"(r) : "r"(a)); return r;
}
__device__ __forceinline__ u32 hadd2(u32 a, u32 b) {
    u32 r; asm("add.f16x2 %0, %1, %2;" : "=r"(r) : "r"(a), "r"(b)); return r;
}
__device__ __forceinline__ void ldsm4(u32* r, u32 a) {
    asm volatile("ldmatrix.sync.aligned.m8n8.x4.shared.b16 {%0,%1,%2,%3}, [%4];"
        : "=r"(r[0]), "=r"(r[1]), "=r"(r[2]), "=r"(r[3]) : "r"(a));
}
__device__ __forceinline__ void ldsm4t(u32* r, u32 a) {
    asm volatile("ldmatrix.sync.aligned.m8n8.x4.trans.shared.b16 {%0,%1,%2,%3}, [%4];"
        : "=r"(r[0]), "=r"(r[1]), "=r"(r[2]), "=r"(r[3]) : "r"(a));
}
__device__ __forceinline__ void mma16(float* c, const u32* a, u32 b0, u32 b1) {
    asm volatile("mma.sync.aligned.m16n8k16.row.col.f32.bf16.bf16.f32 "
        "{%0,%1,%2,%3}, {%4,%5,%6,%7}, {%8,%9}, {%0,%1,%2,%3};"
        : "+f"(c[0]), "+f"(c[1]), "+f"(c[2]), "+f"(c[3])
        : "r"(a[0]), "r"(a[1]), "r"(a[2]), "r"(a[3]), "r"(b0), "r"(b1));
}
__device__ __forceinline__ void mma16h(float* c, const u32* a, u32 b0, u32 b1) {
    asm volatile("mma.sync.aligned.m16n8k16.row.col.f32.f16.f16.f32 "
        "{%0,%1,%2,%3}, {%4,%5,%6,%7}, {%8,%9}, {%0,%1,%2,%3};"
        : "+f"(c[0]), "+f"(c[1]), "+f"(c[2]), "+f"(c[3])
        : "r"(a[0]), "r"(a[1]), "r"(a[2]), "r"(a[3]), "r"(b0), "r"(b1));
}
__device__ __forceinline__ void cpa16(u32 dst, const void* src) {
    asm volatile("cp.async.cg.shared.global [%0], [%1], 16;" :: "r"(dst), "l"(src));
}
#define CP_COMMIT() asm volatile("cp.async.commit_group;" ::: "memory")
#define CP_WAIT(n)  asm volatile("cp.async.wait_group %0;" :: "n"(n) : "memory")

// ---- weight transpose + bf16: Wt[n][k] = W[k][n], 7 matrices ----
__global__ void wtrans(const float* w0, const float* w1, const float* w2, const float* w3,
                       const float* w4, const float* w5, const float* w6, __nv_bfloat16* dst)
{
    __shared__ float t[32][33];
    const float* W;
    switch (blockIdx.z) { case 0: W=w0; break; case 1: W=w1; break; case 2: W=w2; break;
        case 3: W=w3; break; case 4: W=w4; break; case 5: W=w5; break; default: W=w6; }
    int bx = blockIdx.x*32, by = blockIdx.y*32, tx = threadIdx.x, ty = threadIdx.y;
#pragma unroll
    for (int i = 0; i < 4; ++i) t[ty*4+i][tx] = W[(size_t)(by+ty*4+i)*512 + bx+tx];
    __syncthreads();
    __nv_bfloat16* D = dst + (size_t)blockIdx.z*512*512;
#pragma unroll
    for (int i = 0; i < 4; ++i) D[(size_t)(bx+ty*4+i)*512 + by+tx] = __float2bfloat16(t[tx][ty*4+i]);
}

struct GArgs {
    const void* X0[5]; const __nv_bfloat16* W0[5];
    const float* b0[5]; void* Y[5]; float scale[5];
    const void* X1; const __nv_bfloat16* W1; const float* b1;
    const float* res;
};

// ---- HMMA GEMM (R13/R10 config): 2-stage cp.async, 256 thr, warp tile 64x32 ----
// stage stride 36864 B: A [128][72] bf16 @0, B [128][72] bf16 @18432
#define GEMM_SMEM 73728
template<bool AFP32, bool OUTF32>
__global__ __launch_bounds__(256, 2)
void mma_gemm(GArgs a)
{
    extern __shared__ __align__(16) char gsm[];
    const u32 smb = smem_u32(gsm);
    const int tid = threadIdx.x, l = tid & 31, w = tid >> 5, wr = w >> 2, wc = w & 3;
    const int m0 = blockIdx.y*128, n0 = blockIdx.x*128, z = blockIdx.z;
    const void* X0 = a.X0[z]; const __nv_bfloat16* W0 = a.W0[z];
    const float* b0p = a.b0[z]; void* Yout = a.Y[z];
    const float scl = a.scale[z];
    const bool dual = (z == 4);
    const int NCH = dual ? 16 : 8;

    float acc[4][4][4];
#pragma unroll
    for (int i = 0; i < 4; ++i)
#pragma unroll
        for (int j = 0; j < 4; ++j)
#pragma unroll
            for (int q = 0; q < 4; ++q) acc[i][j][q] = 0.0f;

    uint2 aR[8];
    auto ldA = [&](int c) {
        const float* Xf = (const float*)((dual && c >= 8) ? a.X1 : X0);
        const int k0 = (c & 7) * 64;
#pragma unroll
        for (int i = 0; i < 8; ++i) {
            int v = i*256 + tid, row = v >> 4, c4 = v & 15;
            float4 x = *(const float4*)(Xf + (size_t)(m0+row)*512 + k0 + c4*4);
            aR[i] = make_uint2(pack_bf16(x.x,x.y), pack_bf16(x.z,x.w));
        }
    };
    auto stsA = [&](int b) {
        __nv_bfloat16* As = (__nv_bfloat16*)(gsm + b*36864);
#pragma unroll
        for (int i = 0; i < 8; ++i) {
            int v = i*256 + tid, row = v >> 4, c4 = v & 15;
            *(uint2*)(As + row*72 + c4*4) = aR[i];
        }
    };
    auto cpA = [&](int c, int b) {
        const __nv_bfloat16* Xb = (const __nv_bfloat16*)X0;
        const u32 dA = smb + b*36864;
        const int k0 = (c & 7) * 64;
#pragma unroll
        for (int i = 0; i < 4; ++i) {
            int v = i*256 + tid, row = v >> 3, c8 = v & 7;
            cpa16(dA + (row*72 + c8*8)*2, Xb + (size_t)(m0+row)*512 + k0 + c8*8);
        }
    };
    auto cpB = [&](int c, int b) {
        const __nv_bfloat16* W = (dual && c >= 8) ? a.W1 : W0;
        const u32 dB = smb + b*36864 + 18432;
        const int k0 = (c & 7) * 64;
#pragma unroll
        for (int i = 0; i < 4; ++i) {
            int v = i*256 + tid, row = v >> 3, c8 = v & 7;
            cpa16(dB + (row*72 + c8*8)*2, W + (size_t)(n0+row)*512 + k0 + c8*8);
        }
    };

    if (AFP32) { ldA(0); stsA(0); } else cpA(0, 0);
    cpB(0, 0); CP_COMMIT();

#pragma unroll 1
    for (int c = 0; c < NCH; ++c) {
        const int buf = c & 1;
        if (c + 1 < NCH) {
            if (AFP32) ldA(c + 1);
            else cpA(c + 1, buf ^ 1);
            cpB(c + 1, buf ^ 1);
            CP_COMMIT(); CP_WAIT(1);
        } else CP_WAIT(0);
        __syncthreads();

        const u32 sA = smb + buf*36864, sB = sA + 18432;
#pragma unroll
        for (int ks = 0; ks < 4; ++ks) {
            u32 af[4][4];
#pragma unroll
            for (int mi = 0; mi < 4; ++mi)
                ldsm4(af[mi], sA + ((wr*64 + mi*16 + (l & 15))*72 + ks*16 + (l >> 4)*8)*2);
#pragma unroll
            for (int ni = 0; ni < 2; ++ni) {
                u32 bf[4];
                ldsm4(bf, sB + ((wc*32 + ni*16 + (l & 15))*72 + ks*16 + (l >> 4)*8)*2);
#pragma unroll
                for (int mi = 0; mi < 4; ++mi) {
                    mma16(acc[mi][ni*2],   af[mi], bf[0], bf[2]);
                    mma16(acc[mi][ni*2+1], af[mi], bf[1], bf[3]);
                }
            }
        }
        if (AFP32 && c + 1 < NCH) stsA(buf ^ 1);
        __syncthreads();
    }
#pragma unroll
    for (int mi = 0; mi < 4; ++mi)
#pragma unroll
        for (int nj = 0; nj < 4; ++nj) {
            int gr = m0 + wr*64 + mi*16 + (l >> 2);
            int gc = n0 + wc*32 + nj*8 + (l & 3)*2;
            float2 bv = *(const float2*)(b0p + gc);
            if (dual) { float2 b2 = *(const float2*)(a.b1 + gc); bv.x += b2.x; bv.y += b2.y; }
            float* cc = acc[mi][nj];
            if (OUTF32) {
                float* Y = (float*)Yout;
                float2 r0 = *(const float2*)(a.res + (size_t)gr*512 + gc);
                float2 r1 = *(const float2*)(a.res + (size_t)(gr+8)*512 + gc);
                *(float2*)(Y + (size_t)gr*512 + gc)     = make_float2(cc[0]+bv.x+r0.x, cc[1]+bv.y+r0.y);
                *(float2*)(Y + (size_t)(gr+8)*512 + gc) = make_float2(cc[2]+bv.x+r1.x, cc[3]+bv.y+r1.y);
            } else if (dual) {      // V output: fp16
                __half* Y = (__half*)Yout;
                *(u32*)(Y + (size_t)gr*512 + gc)     = f16pack(cc[0]+bv.x, cc[1]+bv.y);
                *(u32*)(Y + (size_t)(gr+8)*512 + gc) = f16pack(cc[2]+bv.x, cc[3]+bv.y);
            } else {
                __nv_bfloat16* Y = (__nv_bfloat16*)Yout;
                *(u32*)(Y + (size_t)gr*512 + gc)     = pack_bf16((cc[0]+bv.x)*scl, (cc[1]+bv.y)*scl);
                *(u32*)(Y + (size_t)(gr+8)*512 + gc) = pack_bf16((cc[2]+bv.x)*scl, (cc[3]+bv.y)*scl);
            }
        }
}

// ---- HMMA flash attention: 4 warps x 32 q; fp16 softmax/PV; pipelined quarters ----
// smem: K0 @0 [128][136], K1 @34816, V0 @69632 [128][72], V1 @88064 ; total 106496
#define ATT_SMEM 106496
__global__ __launch_bounds__(128, 2)
void mma_attn(const __nv_bfloat16* __restrict__ qd, const __nv_bfloat16* __restrict__ qt,
              const __nv_bfloat16* __restrict__ kd, const __nv_bfloat16* __restrict__ kt,
              const __half* __restrict__ vb, __nv_bfloat16* __restrict__ ctx)
{
    extern __shared__ __align__(16) char sm[];
    const u32 smb = smem_u32(sm);
    const int tid = threadIdx.x, l = tid & 31, w = tid >> 5;
    const int q0 = blockIdx.x*128, bh = blockIdx.y, b = bh >> 3, h = bh & 7;
    const size_t rbase = (size_t)b*2048*512 + h*64;

#pragma unroll
    for (int i = 0; i < 16; ++i) {
        int v = i*128 + tid, row = v >> 4, c16 = v & 15;
        const __nv_bfloat16* src = (c16 < 8) ? qd : qt;
        uint4 x = *(const uint4*)(src + rbase + (size_t)(q0+row)*512 + (c16 & 7)*8);
        *(uint4*)(sm + (row*136 + c16*8)*2) = x;
    }
    __syncthreads();
    u32 qf[8][2][4];
#pragma unroll
    for (int ks = 0; ks < 8; ++ks)
#pragma unroll
        for (int mb = 0; mb < 2; ++mb)
            ldsm4(qf[ks][mb], smb + ((w*32 + mb*16 + (l & 15))*136 + ks*16 + (l >> 4)*8)*2);
    __syncthreads();

    auto issue = [&](int kti, int buf) {
        const int k0 = kti*128;
        const u32 dK = smb + buf*34816, dV = smb + 69632 + buf*18432;
#pragma unroll
        for (int i = 0; i < 16; ++i) {
            int v = i*128 + tid, row = v >> 4, c16 = v & 15;
            const __nv_bfloat16* src = (c16 < 8) ? kd : kt;
            cpa16(dK + (row*136 + c16*8)*2, src + rbase + (size_t)(k0+row)*512 + (c16 & 7)*8);
        }
#pragma unroll
        for (int i = 0; i < 8; ++i) {
            int v = i*128 + tid, row = v >> 3, c8 = v & 7;
            cpa16(dV + (row*72 + c8*8)*2, vb + rbase + (size_t)(k0+row)*512 + c8*8);
        }
    };

    float octx[2][8][4];
#pragma unroll
    for (int mb = 0; mb < 2; ++mb)
#pragma unroll
        for (int i = 0; i < 8; ++i)
#pragma unroll
            for (int q = 0; q < 4; ++q) octx[mb][i][q] = 0.0f;
    float ls[2][2] = {{0.f,0.f},{0.f,0.f}};

    issue(0, 0); CP_COMMIT();
#pragma unroll 1
    for (int kti = 0; kti < 16; ++kti) {
        if (kti < 15) { issue(kti+1, (kti+1)&1); CP_COMMIT(); CP_WAIT(1); }
        else CP_WAIT(0);
        __syncthreads();
        const u32 sK = smb + (kti&1)*34816, sV = smb + 69632 + (kti&1)*18432;
        u32 lh[2][2] = {{0u,0u},{0u,0u}};

        float c[2][2][4][4];   // [pipe-buf][mb][i][q]
        // S-MMA for one 32-key quarter into buffer bi
        auto sQK = [&](int qtr, int bi) {
#pragma unroll
            for (int mb = 0; mb < 2; ++mb)
#pragma unroll
                for (int i = 0; i < 4; ++i)
#pragma unroll
                    for (int q = 0; q < 4; ++q) c[bi][mb][i][q] = 0.0f;
#pragma unroll
            for (int ks = 0; ks < 8; ++ks)
#pragma unroll
                for (int kb = 0; kb < 2; ++kb) {
                    u32 bf[4];
                    ldsm4(bf, sK + ((qtr*32 + kb*16 + (l & 15))*136 + ks*16 + (l >> 4)*8)*2);
#pragma unroll
                    for (int mb = 0; mb < 2; ++mb) {
                        mma16(c[bi][mb][kb*2],   qf[ks][mb], bf[0], bf[2]);
                        mma16(c[bi][mb][kb*2+1], qf[ks][mb], bf[1], bf[3]);
                    }
                }
        };

        sQK(0, 0);
#pragma unroll
        for (int qtr = 0; qtr < 4; ++qtr) {
            const int cur = qtr & 1;
            if (qtr < 3) sQK(qtr + 1, cur ^ 1);   // tensor busy while exp below retires
            // softmax on c[cur]: pair-pack -> ex2.f16x2 -> fp16 A-fragment
            u32 pa[2][2][4];
#pragma unroll
            for (int mb = 0; mb < 2; ++mb)
#pragma unroll
                for (int kb = 0; kb < 2; ++kb) {
                    u32 a0 = ex2h2(f16pack(c[cur][mb][kb*2][0],   c[cur][mb][kb*2][1]));
                    u32 a1 = ex2h2(f16pack(c[cur][mb][kb*2][2],   c[cur][mb][kb*2][3]));
                    u32 a2 = ex2h2(f16pack(c[cur][mb][kb*2+1][0], c[cur][mb][kb*2+1][1]));
                    u32 a3 = ex2h2(f16pack(c[cur][mb][kb*2+1][2], c[cur][mb][kb*2+1][3]));
                    lh[mb][0] = hadd2(hadd2(lh[mb][0], a0), a2);
                    lh[mb][1] = hadd2(hadd2(lh[mb][1], a1), a3);
                    pa[mb][kb][0] = a0; pa[mb][kb][1] = a1;
                    pa[mb][kb][2] = a2; pa[mb][kb][3] = a3;
                }
#pragma unroll
            for (int kb = 0; kb < 2; ++kb)
#pragma unroll
                for (int nj4 = 0; nj4 < 4; ++nj4) {
                    u32 bf[4];
                    ldsm4t(bf, sV + ((qtr*32 + kb*16 + (l & 15))*72 + nj4*16 + (l >> 4)*8)*2);
#pragma unroll
                    for (int mb = 0; mb < 2; ++mb) {
                        mma16h(octx[mb][2*nj4],   pa[mb][kb], bf[0], bf[1]);
                        mma16h(octx[mb][2*nj4+1], pa[mb][kb], bf[2], bf[3]);
                    }
                }
        }
#pragma unroll
        for (int mb = 0; mb < 2; ++mb)
#pragma unroll
            for (int j = 0; j < 2; ++j) {
                __half2 hv = *reinterpret_cast<__half2*>(&lh[mb][j]);
                float2 fv = __half22float2(hv);
                ls[mb][j] += fv.x + fv.y;
            }
        __syncthreads();
    }
#pragma unroll
    for (int mb = 0; mb < 2; ++mb) {
        ls[mb][0] += __shfl_xor_sync(0xffffffffu, ls[mb][0], 1);
        ls[mb][0] += __shfl_xor_sync(0xffffffffu, ls[mb][0], 2);
        ls[mb][1] += __shfl_xor_sync(0xffffffffu, ls[mb][1], 1);
        ls[mb][1] += __shfl_xor_sync(0xffffffffu, ls[mb][1], 2);
        float inv0 = 1.0f / ls[mb][0], inv1 = 1.0f / ls[mb][1];
        size_t gr = (size_t)(b*2048 + q0 + w*32 + mb*16 + (l >> 2));
#pragma unroll
        for (int nj = 0; nj < 8; ++nj) {
            int gc = h*64 + nj*8 + (l & 3)*2;
            *(u32*)(ctx + gr*512 + gc)     = pack_bf16(octx[mb][nj][0]*inv0, octx[mb][nj][1]*inv0);
            *(u32*)(ctx + (gr+8)*512 + gc) = pack_bf16(octx[mb][nj][2]*inv1, octx[mb][nj][3]*inv1);
        }
    }
}

// ---- LayerNorm rows of 512 ----
__global__ __launch_bounds__(128)
void layernorm(const float* __restrict__ Y, const float* __restrict__ gamma,
               const float* __restrict__ beta, float* __restrict__ out)
{
    __shared__ float rs[4], rss[4];
    const int row = blockIdx.x, tid = threadIdx.x;
    const size_t off = (size_t)row*512 + tid*4;
    float4 val = *(const float4*)(Y + off);
    float s = val.x + val.y + val.z + val.w;
    float ss = val.x*val.x + val.y*val.y + val.z*val.z + val.w*val.w;
#pragma unroll
    for (int o = 16; o > 0; o >>= 1) { s += __shfl_xor_sync(0xffffffffu, s, o); ss += __shfl_xor_sync(0xffffffffu, ss, o); }
    int wid = tid >> 5;
    if ((tid & 31) == 0) { rs[wid] = s; rss[wid] = ss; }
    __syncthreads();
    s = rs[0]+rs[1]+rs[2]+rs[3]; ss = rss[0]+rss[1]+rss[2]+rss[3];
    float mean = s*(1.0f/512), var = ss*(1.0f/512) - mean*mean, rstd = rsqrtf(var + 1e-5f);
    float4 g = *(const float4*)(gamma + tid*4), be = *(const float4*)(beta + tid*4), o;
    o.x = (val.x-mean)*rstd*g.x + be.x; o.y = (val.y-mean)*rstd*g.y + be.y;
    o.z = (val.z-mean)*rstd*g.z + be.z; o.w = (val.w-mean)*rstd*g.w + be.w;
    *(float4*)(out + off) = o;
}

extern "C" void kernel_launch(void* const* d_in, const int* in_sizes, int n_in,
                              void* d_out, int out_size)
{
    const float* Qd = (const float*)d_in[0];  const float* Qt = (const float*)d_in[1];
    const float* Kd = (const float*)d_in[2];  const float* Kt = (const float*)d_in[3];
    const float* Vd = (const float*)d_in[4];  const float* Vt = (const float*)d_in[5];
    const float* bqd = (const float*)d_in[7];
    const float* bqt = (const float*)d_in[9];
    const float* bkd = (const float*)d_in[11];
    const float* bkt = (const float*)d_in[13];
    const float* bvd = (const float*)d_in[15];
    const float* bvt = (const float*)d_in[17];
    const float* bo  = (const float*)d_in[19];
    const float* gamma = (const float*)d_in[20]; const float* beta = (const float*)d_in[21];
    float* out = (float*)d_out;

    __nv_bfloat16 *wt, *qdb, *qtb, *kdb, *ktb, *ctxb; __half* vbp; float* y;
    cudaGetSymbolAddress((void**)&wt,  g_wt);
    cudaGetSymbolAddress((void**)&qdb, g_qdb);
    cudaGetSymbolAddress((void**)&qtb, g_qtb);
    cudaGetSymbolAddress((void**)&kdb, g_kdb);
    cudaGetSymbolAddress((void**)&ktb, g_ktb);
    cudaGetSymbolAddress((void**)&vbp, g_vb);
    cudaGetSymbolAddress((void**)&ctxb, g_ctx);
    cudaGetSymbolAddress((void**)&y,   g_y);

    cudaFuncSetAttribute(mma_attn, cudaFuncAttributeMaxDynamicSharedMemorySize, ATT_SMEM);
    cudaFuncSetAttribute(mma_gemm<true,false>,  cudaFuncAttributeMaxDynamicSharedMemorySize, GEMM_SMEM);
    cudaFuncSetAttribute(mma_gemm<false,true>,  cudaFuncAttributeMaxDynamicSharedMemorySize, GEMM_SMEM);

    wtrans<<<dim3(16,16,7), dim3(32,8)>>>((const float*)d_in[6], (const float*)d_in[8],
        (const float*)d_in[10], (const float*)d_in[12], (const float*)d_in[14],
        (const float*)d_in[16], (const float*)d_in[18], wt);

    size_t W = (size_t)512*512;
    const float QS = 0.18033688011112042f;   // 0.125 * log2(e)

    GArgs p{};
    p.X0[0]=Qd; p.X0[1]=Qt; p.X0[2]=Kd; p.X0[3]=Kt; p.X0[4]=Vd;
    p.W0[0]=wt; p.W0[1]=wt+W; p.W0[2]=wt+2*W; p.W0[3]=wt+3*W; p.W0[4]=wt+4*W;
    p.b0[0]=bqd; p.b0[1]=bqt; p.b0[2]=bkd; p.b0[3]=bkt; p.b0[4]=bvd;
    p.Y[0]=qdb; p.Y[1]=qtb; p.Y[2]=kdb; p.Y[3]=ktb; p.Y[4]=vbp;
    p.scale[0]=QS; p.scale[1]=QS; p.scale[2]=1.f; p.scale[3]=1.f; p.scale[4]=1.f;
    p.X1=Vt; p.W1=wt+5*W; p.b1=bvt;
    mma_gemm<true,false><<<dim3(4,64,5),256,GEMM_SMEM>>>(p);

    mma_attn<<<dim3(16,32),128,ATT_SMEM>>>(qdb, qtb, kdb, ktb, vbp, ctxb);

    GArgs o{};
    o.X0[0]=ctxb; o.W0[0]=wt+6*W; o.b0[0]=bo; o.Y[0]=y; o.scale[0]=1.f; o.res=Qd;
    mma_gemm<false,true><<<dim3(4,64,1),256,GEMM_SMEM>>>(o);

    layernorm<<<8192,128>>>(y, gamma, beta, out);
}

// round 16
// speedup vs baseline: 1.0188x; 1.0129x over previous
#include <cuda_runtime.h>
#include <cuda_bf16.h>
#include <cuda_fp16.h>
typedef unsigned int u32; typedef unsigned long long u64;

__device__ __align__(16) __nv_bfloat16 g_wt[(size_t)7*512*512];
__device__ __align__(16) __half g_qdb[(size_t)8192*512];
__device__ __align__(16) __half g_qtb[(size_t)8192*512];
__device__ __align__(16) __half g_kdb[(size_t)8192*512];
__device__ __align__(16) __half g_ktb[(size_t)8192*512];
__device__ __align__(16) __half g_vb [(size_t)8192*512];
__device__ __align__(16) __nv_bfloat16 g_ctx[(size_t)8192*512];
__device__ __align__(16) float g_y[(size_t)8192*512];

__device__ __forceinline__ u32 smem_u32(const void* p) {
    u32 a; asm("{ .reg .u64 t; cvta.to.shared.u64 t, %1; cvt.u32.u64 %0, t; }" : "=r"(a) : "l"(p)); return a;
}
__device__ __forceinline__ u32 pack_bf16(float lo, float hi) {
    u32 r; asm("cvt.rn.satfinite.bf16x2.f32 %0, %1, %2;" : "=r"(r) : "f"(hi), "f"(lo)); return r;
}
__device__ __forceinline__ u32 f16pack(float lo, float hi) {
    u32 r; asm("cvt.rn.f16x2.f32 %0, %1, %2;" : "=r"(r) : "f"(hi), "f"(lo)); return r;
}
__device__ __forceinline__ u32 ex2h2(u32 a) {
    u32 r; asm("ex2.approx.f16x2 %0, %1;" : "=r"(r) : "r"(a)); return r;
}
__device__ __forceinline__ u32 hadd2(u32 a, u32 b) {
    u32 r; asm("add.f16x2 %0, %1, %2;" : "=r"(r) : "r"(a), "r"(b)); return r;
}
__device__ __forceinline__ void ldsm4(u32* r, u32 a) {
    asm volatile("ldmatrix.sync.aligned.m8n8.x4.shared.b16 {%0,%1,%2,%3}, [%4];"
        : "=r"(r[0]), "=r"(r[1]), "=r"(r[2]), "=r"(r[3]) : "r"(a));
}
__device__ __forceinline__ void ldsm4t(u32* r, u32 a) {
    asm volatile("ldmatrix.sync.aligned.m8n8.x4.trans.shared.b16 {%0,%1,%2,%3}, [%4];"
        : "=r"(r[0]), "=r"(r[1]), "=r"(r[2]), "=r"(r[3]) : "r"(a));
}
__device__ __forceinline__ void mma16(float* c, const u32* a, u32 b0, u32 b1) {
    asm volatile("mma.sync.aligned.m16n8k16.row.col.f32.bf16.bf16.f32 "
        "{%0,%1,%2,%3}, {%4,%5,%6,%7}, {%8,%9}, {%0,%1,%2,%3};"
        : "+f"(c[0]), "+f"(c[1]), "+f"(c[2]), "+f"(c[3])
        : "r"(a[0]), "r"(a[1]), "r"(a[2]), "r"(a[3]), "r"(b0), "r"(b1));
}
__device__ __forceinline__ void mma16h(float* c, const u32* a, u32 b0, u32 b1) {
    asm volatile("mma.sync.aligned.m16n8k16.row.col.f32.f16.f16.f32 "
        "{%0,%1,%2,%3}, {%4,%5,%6,%7}, {%8,%9}, {%0,%1,%2,%3};"
        : "+f"(c[0]), "+f"(c[1]), "+f"(c[2]), "+f"(c[3])
        : "r"(a[0]), "r"(a[1]), "r"(a[2]), "r"(a[3]), "r"(b0), "r"(b1));
}
// fp16-accumulate QK MMA: packed d-regs feed ex2.f16x2 directly
__device__ __forceinline__ void mma16hh(u32* c, const u32* a, u32 b0, u32 b1) {
    asm volatile("mma.sync.aligned.m16n8k16.row.col.f16.f16.f16.f16 "
        "{%0,%1}, {%2,%3,%4,%5}, {%6,%7}, {%0,%1};"
        : "+r"(c[0]), "+r"(c[1])
        : "r"(a[0]), "r"(a[1]), "r"(a[2]), "r"(a[3]), "r"(b0), "r"(b1));
}
__device__ __forceinline__ void cpa16(u32 dst, const void* src) {
    asm volatile("cp.async.cg.shared.global [%0], [%1], 16;" :: "r"(dst), "l"(src));
}
#define CP_COMMIT() asm volatile("cp.async.commit_group;" ::: "memory")
#define CP_WAIT(n)  asm volatile("cp.async.wait_group %0;" :: "n"(n) : "memory")

// ---- weight transpose + bf16: Wt[n][k] = W[k][n], 7 matrices ----
__global__ void wtrans(const float* w0, const float* w1, const float* w2, const float* w3,
                       const float* w4, const float* w5, const float* w6, __nv_bfloat16* dst)
{
    __shared__ float t[32][33];
    const float* W;
    switch (blockIdx.z) { case 0: W=w0; break; case 1: W=w1; break; case 2: W=w2; break;
        case 3: W=w3; break; case 4: W=w4; break; case 5: W=w5; break; default: W=w6; }
    int bx = blockIdx.x*32, by = blockIdx.y*32, tx = threadIdx.x, ty = threadIdx.y;
#pragma unroll
    for (int i = 0; i < 4; ++i) t[ty*4+i][tx] = W[(size_t)(by+ty*4+i)*512 + bx+tx];
    __syncthreads();
    __nv_bfloat16* D = dst + (size_t)blockIdx.z*512*512;
#pragma unroll
    for (int i = 0; i < 4; ++i) D[(size_t)(bx+ty*4+i)*512 + by+tx] = __float2bfloat16(t[tx][ty*4+i]);
}

struct GArgs {
    const void* X0[5]; const __nv_bfloat16* W0[5];
    const float* b0[5]; void* Y[5]; float scale[5];
    const void* X1; const __nv_bfloat16* W1; const float* b1;
    const float* res;
};

// ---- HMMA GEMM (R13 config): 2-stage cp.async, 256 thr, warp tile 64x32 ----
// stage stride 36864 B: A [128][72] bf16 @0, B [128][72] bf16 @18432
#define GEMM_SMEM 73728
template<bool AFP32, bool OUTF32>
__global__ __launch_bounds__(256, 2)
void mma_gemm(GArgs a)
{
    extern __shared__ __align__(16) char gsm[];
    const u32 smb = smem_u32(gsm);
    const int tid = threadIdx.x, l = tid & 31, w = tid >> 5, wr = w >> 2, wc = w & 3;
    const int m0 = blockIdx.y*128, n0 = blockIdx.x*128, z = blockIdx.z;
    const void* X0 = a.X0[z]; const __nv_bfloat16* W0 = a.W0[z];
    const float* b0p = a.b0[z]; void* Yout = a.Y[z];
    const float scl = a.scale[z];
    const bool dual = (z == 4);
    const int NCH = dual ? 16 : 8;

    float acc[4][4][4];
#pragma unroll
    for (int i = 0; i < 4; ++i)
#pragma unroll
        for (int j = 0; j < 4; ++j)
#pragma unroll
            for (int q = 0; q < 4; ++q) acc[i][j][q] = 0.0f;

    uint2 aR[8];
    auto ldA = [&](int c) {
        const float* Xf = (const float*)((dual && c >= 8) ? a.X1 : X0);
        const int k0 = (c & 7) * 64;
#pragma unroll
        for (int i = 0; i < 8; ++i) {
            int v = i*256 + tid, row = v >> 4, c4 = v & 15;
            float4 x = *(const float4*)(Xf + (size_t)(m0+row)*512 + k0 + c4*4);
            aR[i] = make_uint2(pack_bf16(x.x,x.y), pack_bf16(x.z,x.w));
        }
    };
    auto stsA = [&](int b) {
        __nv_bfloat16* As = (__nv_bfloat16*)(gsm + b*36864);
#pragma unroll
        for (int i = 0; i < 8; ++i) {
            int v = i*256 + tid, row = v >> 4, c4 = v & 15;
            *(uint2*)(As + row*72 + c4*4) = aR[i];
        }
    };
    auto cpA = [&](int c, int b) {
        const __nv_bfloat16* Xb = (const __nv_bfloat16*)X0;
        const u32 dA = smb + b*36864;
        const int k0 = (c & 7) * 64;
#pragma unroll
        for (int i = 0; i < 4; ++i) {
            int v = i*256 + tid, row = v >> 3, c8 = v & 7;
            cpa16(dA + (row*72 + c8*8)*2, Xb + (size_t)(m0+row)*512 + k0 + c8*8);
        }
    };
    auto cpB = [&](int c, int b) {
        const __nv_bfloat16* W = (dual && c >= 8) ? a.W1 : W0;
        const u32 dB = smb + b*36864 + 18432;
        const int k0 = (c & 7) * 64;
#pragma unroll
        for (int i = 0; i < 4; ++i) {
            int v = i*256 + tid, row = v >> 3, c8 = v & 7;
            cpa16(dB + (row*72 + c8*8)*2, W + (size_t)(n0+row)*512 + k0 + c8*8);
        }
    };

    if (AFP32) { ldA(0); stsA(0); } else cpA(0, 0);
    cpB(0, 0); CP_COMMIT();

#pragma unroll 1
    for (int c = 0; c < NCH; ++c) {
        const int buf = c & 1;
        if (c + 1 < NCH) {
            if (AFP32) ldA(c + 1);
            else cpA(c + 1, buf ^ 1);
            cpB(c + 1, buf ^ 1);
            CP_COMMIT(); CP_WAIT(1);
        } else CP_WAIT(0);
        __syncthreads();

        const u32 sA = smb + buf*36864, sB = sA + 18432;
#pragma unroll
        for (int ks = 0; ks < 4; ++ks) {
            u32 af[4][4];
#pragma unroll
            for (int mi = 0; mi < 4; ++mi)
                ldsm4(af[mi], sA + ((wr*64 + mi*16 + (l & 15))*72 + ks*16 + (l >> 4)*8)*2);
#pragma unroll
            for (int ni = 0; ni < 2; ++ni) {
                u32 bf[4];
                ldsm4(bf, sB + ((wc*32 + ni*16 + (l & 15))*72 + ks*16 + (l >> 4)*8)*2);
#pragma unroll
                for (int mi = 0; mi < 4; ++mi) {
                    mma16(acc[mi][ni*2],   af[mi], bf[0], bf[2]);
                    mma16(acc[mi][ni*2+1], af[mi], bf[1], bf[3]);
                }
            }
        }
        if (AFP32 && c + 1 < NCH) stsA(buf ^ 1);
        __syncthreads();
    }
#pragma unroll
    for (int mi = 0; mi < 4; ++mi)
#pragma unroll
        for (int nj = 0; nj < 4; ++nj) {
            int gr = m0 + wr*64 + mi*16 + (l >> 2);
            int gc = n0 + wc*32 + nj*8 + (l & 3)*2;
            float2 bv = *(const float2*)(b0p + gc);
            if (dual) { float2 b2 = *(const float2*)(a.b1 + gc); bv.x += b2.x; bv.y += b2.y; }
            float* cc = acc[mi][nj];
            if (OUTF32) {
                float* Y = (float*)Yout;
                float2 r0 = *(const float2*)(a.res + (size_t)gr*512 + gc);
                float2 r1 = *(const float2*)(a.res + (size_t)(gr+8)*512 + gc);
                *(float2*)(Y + (size_t)gr*512 + gc)     = make_float2(cc[0]+bv.x+r0.x, cc[1]+bv.y+r0.y);
                *(float2*)(Y + (size_t)(gr+8)*512 + gc) = make_float2(cc[2]+bv.x+r1.x, cc[3]+bv.y+r1.y);
            } else {                 // q/k/v outputs: fp16 (scale pre-folded for q)
                __half* Y = (__half*)Yout;
                *(u32*)(Y + (size_t)gr*512 + gc)     = f16pack((cc[0]+bv.x)*scl, (cc[1]+bv.y)*scl);
                *(u32*)(Y + (size_t)(gr+8)*512 + gc) = f16pack((cc[2]+bv.x)*scl, (cc[3]+bv.y)*scl);
            }
        }
}

// ---- HMMA flash attention: 4 warps x 32 q; fp16 QK-acc + ex2.f16x2 softmax ----
// smem: K0 @0 [128][136], K1 @34816, V0 @69632 [128][72], V1 @88064 ; total 106496
#define ATT_SMEM 106496
__global__ __launch_bounds__(128, 2)
void mma_attn(const __half* __restrict__ qd, const __half* __restrict__ qt,
              const __half* __restrict__ kd, const __half* __restrict__ kt,
              const __half* __restrict__ vb, __nv_bfloat16* __restrict__ ctx)
{
    extern __shared__ __align__(16) char sm[];
    const u32 smb = smem_u32(sm);
    const int tid = threadIdx.x, l = tid & 31, w = tid >> 5;
    const int q0 = blockIdx.x*128, bh = blockIdx.y, b = bh >> 3, h = bh & 7;
    const size_t rbase = (size_t)b*2048*512 + h*64;

#pragma unroll
    for (int i = 0; i < 16; ++i) {
        int v = i*128 + tid, row = v >> 4, c16 = v & 15;
        const __half* src = (c16 < 8) ? qd : qt;
        uint4 x = *(const uint4*)(src + rbase + (size_t)(q0+row)*512 + (c16 & 7)*8);
        *(uint4*)(sm + (row*136 + c16*8)*2) = x;
    }
    __syncthreads();
    u32 qf[8][2][4];
#pragma unroll
    for (int ks = 0; ks < 8; ++ks)
#pragma unroll
        for (int mb = 0; mb < 2; ++mb)
            ldsm4(qf[ks][mb], smb + ((w*32 + mb*16 + (l & 15))*136 + ks*16 + (l >> 4)*8)*2);
    __syncthreads();

    auto issue = [&](int kti, int buf) {
        const int k0 = kti*128;
        const u32 dK = smb + buf*34816, dV = smb + 69632 + buf*18432;
#pragma unroll
        for (int i = 0; i < 16; ++i) {
            int v = i*128 + tid, row = v >> 4, c16 = v & 15;
            const __half* src = (c16 < 8) ? kd : kt;
            cpa16(dK + (row*136 + c16*8)*2, src + rbase + (size_t)(k0+row)*512 + (c16 & 7)*8);
        }
#pragma unroll
        for (int i = 0; i < 8; ++i) {
            int v = i*128 + tid, row = v >> 3, c8 = v & 7;
            cpa16(dV + (row*72 + c8*8)*2, vb + rbase + (size_t)(k0+row)*512 + c8*8);
        }
    };

    float octx[2][8][4];
#pragma unroll
    for (int mb = 0; mb < 2; ++mb)
#pragma unroll
        for (int i = 0; i < 8; ++i)
#pragma unroll
            for (int q = 0; q < 4; ++q) octx[mb][i][q] = 0.0f;
    float ls[2][2] = {{0.f,0.f},{0.f,0.f}};

    issue(0, 0); CP_COMMIT();
#pragma unroll 1
    for (int kti = 0; kti < 16; ++kti) {
        if (kti < 15) { issue(kti+1, (kti+1)&1); CP_COMMIT(); CP_WAIT(1); }
        else CP_WAIT(0);
        __syncthreads();
        const u32 sK = smb + (kti&1)*34816, sV = smb + 69632 + (kti&1)*18432;
        u32 lh[2][2] = {{0u,0u},{0u,0u}};

#pragma unroll
        for (int qtr = 0; qtr < 4; ++qtr) {
            u32 c[2][4][2];   // fp16x2 accumulators: [mb][n8-tile][reg]
#pragma unroll
            for (int mb = 0; mb < 2; ++mb)
#pragma unroll
                for (int i = 0; i < 4; ++i) { c[mb][i][0] = 0u; c[mb][i][1] = 0u; }
#pragma unroll
            for (int ks = 0; ks < 8; ++ks)
#pragma unroll
                for (int kb = 0; kb < 2; ++kb) {
                    u32 bf[4];
                    ldsm4(bf, sK + ((qtr*32 + kb*16 + (l & 15))*136 + ks*16 + (l >> 4)*8)*2);
#pragma unroll
                    for (int mb = 0; mb < 2; ++mb) {
                        mma16hh(c[mb][kb*2],   qf[ks][mb], bf[0], bf[2]);
                        mma16hh(c[mb][kb*2+1], qf[ks][mb], bf[1], bf[3]);
                    }
                }
            // softmax: ex2.f16x2 directly on packed fp16 scores -> PV A-fragments
            u32 pa[2][2][4];
#pragma unroll
            for (int mb = 0; mb < 2; ++mb)
#pragma unroll
                for (int kb = 0; kb < 2; ++kb) {
                    u32 a0 = ex2h2(c[mb][2*kb][0]);     // row r,   keys kb*16+0..7
                    u32 a1 = ex2h2(c[mb][2*kb][1]);     // row r+8, keys kb*16+0..7
                    u32 a2 = ex2h2(c[mb][2*kb+1][0]);   // row r,   keys kb*16+8..15
                    u32 a3 = ex2h2(c[mb][2*kb+1][1]);   // row r+8, keys kb*16+8..15
                    lh[mb][0] = hadd2(hadd2(lh[mb][0], a0), a2);
                    lh[mb][1] = hadd2(hadd2(lh[mb][1], a1), a3);
                    pa[mb][kb][0] = a0; pa[mb][kb][1] = a1;
                    pa[mb][kb][2] = a2; pa[mb][kb][3] = a3;
                }
#pragma unroll
            for (int kb = 0; kb < 2; ++kb)
#pragma unroll
                for (int nj4 = 0; nj4 < 4; ++nj4) {
                    u32 bf[4];
                    ldsm4t(bf, sV + ((qtr*32 + kb*16 + (l & 15))*72 + nj4*16 + (l >> 4)*8)*2);
#pragma unroll
                    for (int mb = 0; mb < 2; ++mb) {
                        mma16h(octx[mb][2*nj4],   pa[mb][kb], bf[0], bf[1]);
                        mma16h(octx[mb][2*nj4+1], pa[mb][kb], bf[2], bf[3]);
                    }
                }
        }
#pragma unroll
        for (int mb = 0; mb < 2; ++mb)
#pragma unroll
            for (int j = 0; j < 2; ++j) {
                __half2 hv = *reinterpret_cast<__half2*>(&lh[mb][j]);
                float2 fv = __half22float2(hv);
                ls[mb][j] += fv.x + fv.y;
            }
        __syncthreads();
    }
#pragma unroll
    for (int mb = 0; mb < 2; ++mb) {
        ls[mb][0] += __shfl_xor_sync(0xffffffffu, ls[mb][0], 1);
        ls[mb][0] += __shfl_xor_sync(0xffffffffu, ls[mb][0], 2);
        ls[mb][1] += __shfl_xor_sync(0xffffffffu, ls[mb][1], 1);
        ls[mb][1] += __shfl_xor_sync(0xffffffffu, ls[mb][1], 2);
        float inv0 = 1.0f / ls[mb][0], inv1 = 1.0f / ls[mb][1];
        size_t gr = (size_t)(b*2048 + q0 + w*32 + mb*16 + (l >> 2));
#pragma unroll
        for (int nj = 0; nj < 8; ++nj) {
            int gc = h*64 + nj*8 + (l & 3)*2;
            *(u32*)(ctx + gr*512 + gc)     = pack_bf16(octx[mb][nj][0]*inv0, octx[mb][nj][1]*inv0);
            *(u32*)(ctx + (gr+8)*512 + gc) = pack_bf16(octx[mb][nj][2]*inv1, octx[mb][nj][3]*inv1);
        }
    }
}

// ---- LayerNorm rows of 512 ----
__global__ __launch_bounds__(128)
void layernorm(const float* __restrict__ Y, const float* __restrict__ gamma,
               const float* __restrict__ beta, float* __restrict__ out)
{
    __shared__ float rs[4], rss[4];
    const int row = blockIdx.x, tid = threadIdx.x;
    const size_t off = (size_t)row*512 + tid*4;
    float4 val = *(const float4*)(Y + off);
    float s = val.x + val.y + val.z + val.w;
    float ss = val.x*val.x + val.y*val.y + val.z*val.z + val.w*val.w;
#pragma unroll
    for (int o = 16; o > 0; o >>= 1) { s += __shfl_xor_sync(0xffffffffu, s, o); ss += __shfl_xor_sync(0xffffffffu, ss, o); }
    int wid = tid >> 5;
    if ((tid & 31) == 0) { rs[wid] = s; rss[wid] = ss; }
    __syncthreads();
    s = rs[0]+rs[1]+rs[2]+rs[3]; ss = rss[0]+rss[1]+rss[2]+rss[3];
    float mean = s*(1.0f/512), var = ss*(1.0f/512) - mean*mean, rstd = rsqrtf(var + 1e-5f);
    float4 g = *(const float4*)(gamma + tid*4), be = *(const float4*)(beta + tid*4), o;
    o.x = (val.x-mean)*rstd*g.x + be.x; o.y = (val.y-mean)*rstd*g.y + be.y;
    o.z = (val.z-mean)*rstd*g.z + be.z; o.w = (val.w-mean)*rstd*g.w + be.w;
    *(float4*)(out + off) = o;
}

extern "C" void kernel_launch(void* const* d_in, const int* in_sizes, int n_in,
                              void* d_out, int out_size)
{
    const float* Qd = (const float*)d_in[0];  const float* Qt = (const float*)d_in[1];
    const float* Kd = (const float*)d_in[2];  const float* Kt = (const float*)d_in[3];
    const float* Vd = (const float*)d_in[4];  const float* Vt = (const float*)d_in[5];
    const float* bqd = (const float*)d_in[7];
    const float* bqt = (const float*)d_in[9];
    const float* bkd = (const float*)d_in[11];
    const float* bkt = (const float*)d_in[13];
    const float* bvd = (const float*)d_in[15];
    const float* bvt = (const float*)d_in[17];
    const float* bo  = (const float*)d_in[19];
    const float* gamma = (const float*)d_in[20]; const float* beta = (const float*)d_in[21];
    float* out = (float*)d_out;

    __nv_bfloat16 *wt, *ctxb; __half *qdb, *qtb, *kdb, *ktb, *vbp; float* y;
    cudaGetSymbolAddress((void**)&wt,  g_wt);
    cudaGetSymbolAddress((void**)&qdb, g_qdb);
    cudaGetSymbolAddress((void**)&qtb, g_qtb);
    cudaGetSymbolAddress((void**)&kdb, g_kdb);
    cudaGetSymbolAddress((void**)&ktb, g_ktb);
    cudaGetSymbolAddress((void**)&vbp, g_vb);
    cudaGetSymbolAddress((void**)&ctxb, g_ctx);
    cudaGetSymbolAddress((void**)&y,   g_y);

    cudaFuncSetAttribute(mma_attn, cudaFuncAttributeMaxDynamicSharedMemorySize, ATT_SMEM);
    cudaFuncSetAttribute(mma_gemm<true,false>,  cudaFuncAttributeMaxDynamicSharedMemorySize, GEMM_SMEM);
    cudaFuncSetAttribute(mma_gemm<false,true>,  cudaFuncAttributeMaxDynamicSharedMemorySize, GEMM_SMEM);

    wtrans<<<dim3(16,16,7), dim3(32,8)>>>((const float*)d_in[6], (const float*)d_in[8],
        (const float*)d_in[10], (const float*)d_in[12], (const float*)d_in[14],
        (const float*)d_in[16], (const float*)d_in[18], wt);

    size_t W = (size_t)512*512;
    const float QS = 0.18033688011112042f;   // 0.125 * log2(e)

    GArgs p{};
    p.X0[0]=Qd; p.X0[1]=Qt; p.X0[2]=Kd; p.X0[3]=Kt; p.X0[4]=Vd;
    p.W0[0]=wt; p.W0[1]=wt+W; p.W0[2]=wt+2*W; p.W0[3]=wt+3*W; p.W0[4]=wt+4*W;
    p.b0[0]=bqd; p.b0[1]=bqt; p.b0[2]=bkd; p.b0[3]=bkt; p.b0[4]=bvd;
    p.Y[0]=qdb; p.Y[1]=qtb; p.Y[2]=kdb; p.Y[3]=ktb; p.Y[4]=vbp;
    p.scale[0]=QS; p.scale[1]=QS; p.scale[2]=1.f; p.scale[3]=1.f; p.scale[4]=1.f;
    p.X1=Vt; p.W1=wt+5*W; p.b1=bvt;
    mma_gemm<true,false><<<dim3(4,64,5),256,GEMM_SMEM>>>(p);

    mma_attn<<<dim3(16,32),128,ATT_SMEM>>>(qdb, qtb, kdb, ktb, vbp, ctxb);

    GArgs o{};
    o.X0[0]=ctxb; o.W0[0]=wt+6*W; o.b0[0]=bo; o.Y[0]=y; o.scale[0]=1.f; o.res=Qd;
    mma_gemm<false,true><<<dim3(4,64,1),256,GEMM_SMEM>>>(o);

    layernorm<<<8192,128>>>(y, gamma, beta, out);
}